// round 14
// baseline (speedup 1.0000x reference)
#include <cuda_runtime.h>
#include <cuda_bf16.h>
#include <float.h>
#include <stdint.h>

// VectorQuantize: z[16,256,32,32] f32, codebook[8192,256] f32
// bf16 mma.sync GEMM (64x64 warp tile, frag-pipelined mainloop) -> summaries
// -> warp/row select + exact fp32 refine -> transposed gather.

#define NPTS 16384
#define NC   256
#define NK   8192
#define ZQ_ELEMS 4194304
#define TM 128
#define TN 128
#define NTILE (NK / TN)      // 64
#define MARGIN 8e-3f

// ---------------- scratch ----------------
__device__ unsigned short g_ah[NPTS * NC];    // bf16(z)
__device__ unsigned short g_bh[NK * NC];      // bf16(-2cb)
__device__ float g_zf[NPTS * NC];             // fp32 z rows (refine)
__device__ float g_zn[NPTS];
__device__ float g_cn[NK];                    // |cb|^2
__device__ float g_tmin[(size_t)NPTS * NTILE];
__device__ unsigned g_tmask[(size_t)NPTS * NTILE * 4];
__device__ int g_idx[NPTS];

// smem layout for vq_gemm
#define SROWMIN 65536   // 128 x u32
#define SMASK   66048   // 128 x 4 x u32
#define SMEM_SZ 68608

// ---------------- PTX helpers ----------------
__device__ __forceinline__ uint32_t smem_u32(const void* p) {
    uint32_t a;
    asm("{ .reg .u64 t; cvta.to.shared.u64 t, %1; cvt.u32.u64 %0, t; }" : "=r"(a) : "l"(p));
    return a;
}
#define CP_ASYNC16(sm, gp) \
    asm volatile("cp.async.cg.shared.global [%0], [%1], 16;" :: "r"(sm), "l"(gp) : "memory")
#define CP_COMMIT() asm volatile("cp.async.commit_group;" ::: "memory")
#define CP_WAIT(n)  asm volatile("cp.async.wait_group %0;" :: "n"(n) : "memory")
#define LDSM_X4(r0, r1, r2, r3, ad) \
    asm volatile("ldmatrix.sync.aligned.m8n8.x4.shared.b16 {%0,%1,%2,%3}, [%4];" \
                 : "=r"(r0), "=r"(r1), "=r"(r2), "=r"(r3) : "r"(ad))
#define MMA16816(d, a0, a1, a2, a3, b0, b1) \
    asm volatile("mma.sync.aligned.m16n8k16.row.col.f32.bf16.bf16.f32 " \
                 "{%0,%1,%2,%3}, {%4,%5,%6,%7}, {%8,%9}, {%0,%1,%2,%3};" \
                 : "+f"((d)[0]), "+f"((d)[1]), "+f"((d)[2]), "+f"((d)[3]) \
                 : "r"(a0), "r"(a1), "r"(a2), "r"(a3), "r"(b0), "r"(b1))

__device__ __forceinline__ uint32_t fenc(float f) {
    uint32_t b = __float_as_uint(f);
    return (b & 0x80000000u) ? ~b : (b | 0x80000000u);
}
__device__ __forceinline__ float fdec(uint32_t u) {
    uint32_t b = (u & 0x80000000u) ? (u & 0x7FFFFFFFu) : ~u;
    return __uint_as_float(b);
}

// ---------------- prep_cb: warp per row, vectorized ----------------
__global__ void __launch_bounds__(256) prep_cb(const float* __restrict__ cb) {
    const int lane = threadIdx.x & 31, wid = threadIdx.x >> 5;
    const int k = blockIdx.x * 8 + wid;
    const float4* row = (const float4*)(cb + (size_t)k * NC);
    float4 v0 = row[lane * 2], v1 = row[lane * 2 + 1];
    float s = v0.x * v0.x + v0.y * v0.y + v0.z * v0.z + v0.w * v0.w
            + v1.x * v1.x + v1.y * v1.y + v1.z * v1.z + v1.w * v1.w;
    uint4 pk;
    {
        uint32_t a, b, c, d;
        asm("cvt.rn.bf16x2.f32 %0, %1, %2;" : "=r"(a) : "f"(-2.0f * v0.y), "f"(-2.0f * v0.x));
        asm("cvt.rn.bf16x2.f32 %0, %1, %2;" : "=r"(b) : "f"(-2.0f * v0.w), "f"(-2.0f * v0.z));
        asm("cvt.rn.bf16x2.f32 %0, %1, %2;" : "=r"(c) : "f"(-2.0f * v1.y), "f"(-2.0f * v1.x));
        asm("cvt.rn.bf16x2.f32 %0, %1, %2;" : "=r"(d) : "f"(-2.0f * v1.w), "f"(-2.0f * v1.z));
        pk.x = a; pk.y = b; pk.z = c; pk.w = d;
    }
    *(uint4*)(g_bh + (size_t)k * NC + lane * 8) = pk;
#pragma unroll
    for (int o = 16; o > 0; o >>= 1) s += __shfl_xor_sync(0xffffffffu, s, o);
    if (lane == 0) g_cn[k] = s;
}

// ---------------- prep_z: transposed, coalesced both sides ----------------
__global__ void __launch_bounds__(256) prep_z(const float* __restrict__ z) {
    __shared__ float S[256][33];
    const int t = threadIdx.x, lane = t & 31, wid = t >> 5;
    const int b = blockIdx.y, hw0 = blockIdx.x * 32;
    const float* zb = z + ((size_t)b << 18);
#pragma unroll
    for (int i = 0; i < 32; i++) {
        const int c = i * 8 + wid;
        S[c][lane] = zb[(c << 10) + hw0 + lane];
    }
    __syncthreads();
#pragma unroll
    for (int r = 0; r < 4; r++) {
        const int nl = r * 8 + wid;
        const int n = (b << 10) + hw0 + nl;
        float sum = 0.f;
#pragma unroll
        for (int j = 0; j < 8; j++) {
            const int c = lane + 32 * j;
            const float v = S[c][nl];
            sum += v * v;
            g_zf[(size_t)n * NC + c] = v;
            __nv_bfloat16 h = __float2bfloat16_rn(v);
            g_ah[(size_t)n * NC + c] = *(unsigned short*)&h;
        }
#pragma unroll
        for (int o = 16; o > 0; o >>= 1) sum += __shfl_xor_sync(0xffffffffu, sum, o);
        if (lane == 0) g_zn[n] = sum;
    }
}

// ---------------- GEMM: 128x128 CTA, 4 warps 64x64, frag-pipelined ----------------
__device__ __forceinline__ void issue_loads(uint32_t sb, int buf,
                                            const unsigned short* A, const unsigned short* B,
                                            int kchunk, int t) {
    uint32_t ab = sb + buf * 32768;
    uint32_t bb = ab + 16384;
#pragma unroll
    for (int i = 0; i < 8; i++) {
        int e = i * 128 + t;
        int r = e >> 3, ck = e & 7;
        int sw = (ck * 16) ^ ((r & 7) * 16);
        CP_ASYNC16(ab + r * 128 + sw, A + (size_t)r * NC + kchunk * 64 + ck * 8);
        CP_ASYNC16(bb + r * 128 + sw, B + (size_t)r * NC + kchunk * 64 + ck * 8);
    }
}

__global__ void __launch_bounds__(128, 2) vq_gemm() {
    extern __shared__ char smem[];
    const uint32_t sb = smem_u32(smem);
    const int t = threadIdx.x;
    const int lane = t & 31, wid = t >> 5;
    const int warp_m = wid >> 1, warp_n = wid & 1;   // 2x2 warps -> 64x64 per warp
    const int tile = blockIdx.x;
    const int col0 = tile * TN;
    const int row0 = blockIdx.y * TM;
    const unsigned short* A = g_ah + (size_t)row0 * NC;
    const unsigned short* B = g_bh + (size_t)col0 * NC;

    uint32_t* rowmin = (uint32_t*)(smem + SROWMIN);
    uint32_t* maskw  = (uint32_t*)(smem + SMASK);
    rowmin[t] = fenc(FLT_MAX);
#pragma unroll
    for (int i = 0; i < 4; i++) maskw[i * 128 + t] = 0;

    float d[4][8][4];
#pragma unroll
    for (int i = 0; i < 4; i++)
#pragma unroll
        for (int j = 0; j < 8; j++)
#pragma unroll
            for (int q = 0; q < 4; q++) d[i][j][q] = 0.f;

    issue_loads(sb, 0, A, B, 0, t);
    CP_COMMIT();

    const int arow = (lane & 15);   // fragment row within 16
    for (int kc = 0; kc < 4; kc++) {
        if (kc < 3) {
            issue_loads(sb, (kc + 1) & 1, A, B, kc + 1, t);
            CP_COMMIT();
            CP_WAIT(1);
        } else {
            CP_WAIT(0);
        }
        __syncthreads();

        const uint32_t Ab = sb + (kc & 1) * 32768;
        const uint32_t Bb = Ab + 16384;

        uint32_t a[2][4][4], bq[2][4][4];   // frag double-buffer across ks
        // prime ks=0
        {
            const int c2 = (lane >> 4) * 16;
#pragma unroll
            for (int mt = 0; mt < 4; mt++) {
                int row = warp_m * 64 + mt * 16 + arow;
                LDSM_X4(a[0][mt][0], a[0][mt][1], a[0][mt][2], a[0][mt][3],
                        Ab + row * 128 + (c2 ^ ((row & 7) * 16)));
            }
#pragma unroll
            for (int np = 0; np < 4; np++) {
                int brow = warp_n * 64 + np * 16 + arow;
                LDSM_X4(bq[0][np][0], bq[0][np][1], bq[0][np][2], bq[0][np][3],
                        Bb + brow * 128 + (c2 ^ ((brow & 7) * 16)));
            }
        }
#pragma unroll
        for (int ks = 0; ks < 4; ks++) {
            const int cur = ks & 1, nxt = cur ^ 1;
            if (ks < 3) {   // prefetch next ks frags before this ks's MMAs
                const int c2 = (ks + 1) * 32 + (lane >> 4) * 16;
#pragma unroll
                for (int mt = 0; mt < 4; mt++) {
                    int row = warp_m * 64 + mt * 16 + arow;
                    LDSM_X4(a[nxt][mt][0], a[nxt][mt][1], a[nxt][mt][2], a[nxt][mt][3],
                            Ab + row * 128 + (c2 ^ ((row & 7) * 16)));
                }
#pragma unroll
                for (int np = 0; np < 4; np++) {
                    int brow = warp_n * 64 + np * 16 + arow;
                    LDSM_X4(bq[nxt][np][0], bq[nxt][np][1], bq[nxt][np][2], bq[nxt][np][3],
                            Bb + brow * 128 + (c2 ^ ((brow & 7) * 16)));
                }
            }
#pragma unroll
            for (int mt = 0; mt < 4; mt++)
#pragma unroll
                for (int np = 0; np < 4; np++) {
                    MMA16816(d[mt][np * 2],     a[cur][mt][0], a[cur][mt][1], a[cur][mt][2], a[cur][mt][3],
                             bq[cur][np][0], bq[cur][np][2]);
                    MMA16816(d[mt][np * 2 + 1], a[cur][mt][0], a[cur][mt][1], a[cur][mt][2], a[cur][mt][3],
                             bq[cur][np][1], bq[cur][np][3]);
                }
        }
        __syncthreads();
    }

    // ---- summary epilogue ----
    const int g = lane >> 2, tig = lane & 3;
#pragma unroll
    for (int nt = 0; nt < 8; nt++) {
        const int scol = col0 + warp_n * 64 + nt * 8 + 2 * tig;
        const float cn0 = __ldg(&g_cn[scol]);
        const float cn1 = __ldg(&g_cn[scol + 1]);
#pragma unroll
        for (int mt = 0; mt < 4; mt++) {
            d[mt][nt][0] += cn0; d[mt][nt][1] += cn1;
            d[mt][nt][2] += cn0; d[mt][nt][3] += cn1;
        }
    }
#pragma unroll
    for (int mt = 0; mt < 4; mt++) {
        const int r0 = warp_m * 64 + mt * 16 + g;
        float mn0 = FLT_MAX, mn1 = FLT_MAX;
#pragma unroll
        for (int nt = 0; nt < 8; nt++) {
            mn0 = fminf(mn0, fminf(d[mt][nt][0], d[mt][nt][1]));
            mn1 = fminf(mn1, fminf(d[mt][nt][2], d[mt][nt][3]));
        }
        atomicMin(&rowmin[r0],     fenc(mn0));
        atomicMin(&rowmin[r0 + 8], fenc(mn1));
    }
    __syncthreads();
#pragma unroll
    for (int mt = 0; mt < 4; mt++) {
        const int r0 = warp_m * 64 + mt * 16 + g;
        const float th0 = fdec(rowmin[r0]) + MARGIN;
        const float th1 = fdec(rowmin[r0 + 8]) + MARGIN;
#pragma unroll
        for (int nt = 0; nt < 8; nt++) {
            const int c = warp_n * 64 + nt * 8 + 2 * tig;
            if (d[mt][nt][0] <= th0) atomicOr(&maskw[r0 * 4 + (c >> 5)], 1u << (c & 31));
            if (d[mt][nt][1] <= th0) atomicOr(&maskw[r0 * 4 + ((c + 1) >> 5)], 1u << ((c + 1) & 31));
            if (d[mt][nt][2] <= th1) atomicOr(&maskw[(r0 + 8) * 4 + (c >> 5)], 1u << (c & 31));
            if (d[mt][nt][3] <= th1) atomicOr(&maskw[(r0 + 8) * 4 + ((c + 1) >> 5)], 1u << ((c + 1) & 31));
        }
    }
    __syncthreads();
    g_tmin[(size_t)(row0 + t) * NTILE + tile] = fdec(rowmin[t]);
#pragma unroll
    for (int i = 0; i < 4; i++) {
        int e = i * 128 + t;
        int r = e >> 2, w = e & 3;
        g_tmask[((size_t)(row0 + r) * NTILE + tile) * 4 + w] = maskw[r * 4 + w];
    }
}

// ---------------- select + exact fp32 refine: one warp per row ----------------
__global__ void __launch_bounds__(256) vq_select(const float* __restrict__ cb) {
    const int lane = threadIdx.x & 31;
    const int row = blockIdx.x * 8 + (threadIdx.x >> 5);

    const float* tm = g_tmin + (size_t)row * NTILE;
    const float v0 = tm[lane], v1 = tm[lane + 32];
    float m = fminf(v0, v1);
#pragma unroll
    for (int o = 16; o > 0; o >>= 1) m = fminf(m, __shfl_xor_sync(0xffffffffu, m, o));
    const float thr = m + MARGIN;

    float z8[8];
#pragma unroll
    for (int i = 0; i < 8; i++) z8[i] = g_zf[(size_t)row * NC + lane * 8 + i];
    const float zn = g_zn[row];

    float bv = FLT_MAX;
    int bi = 0x7fffffff;

    unsigned bal[2];
    bal[0] = __ballot_sync(0xffffffffu, v0 <= thr);
    bal[1] = __ballot_sync(0xffffffffu, v1 <= thr);
#pragma unroll
    for (int p = 0; p < 2; p++) {
        unsigned bits = bal[p];
        while (bits) {
            const int tile = p * 32 + (__ffs(bits) - 1);
            bits &= bits - 1;
            const uint4 mk = *(const uint4*)(g_tmask + ((size_t)row * NTILE + tile) * 4);
            unsigned w[4] = { mk.x, mk.y, mk.z, mk.w };
#pragma unroll
            for (int wi = 0; wi < 4; wi++) {
                unsigned ww = w[wi];
                while (ww) {
                    const int b = __ffs(ww) - 1;
                    ww &= ww - 1;
                    const int k = tile * TN + wi * 32 + b;
                    const float* cbr = cb + (size_t)k * NC + lane * 8;
                    float s = 0.f;
#pragma unroll
                    for (int i = 0; i < 8; i++) s = fmaf(z8[i], -2.0f * cbr[i], s);
#pragma unroll
                    for (int o = 16; o > 0; o >>= 1) s += __shfl_xor_sync(0xffffffffu, s, o);
                    const float dd = (s + zn) + g_cn[k];
                    if (dd < bv || (dd == bv && k < bi)) { bv = dd; bi = k; }
                }
            }
        }
    }
    if (lane == 0) g_idx[row] = bi;
}

// ---------------- transposed gather ----------------
__global__ void __launch_bounds__(256) vq_gather(const float* __restrict__ cb,
                                                 float* __restrict__ out) {
    __shared__ float S[256][33];
    __shared__ int sidx[32];
    const int t = threadIdx.x, lane = t & 31, wid = t >> 5;
    const int b = blockIdx.y, hw0 = blockIdx.x * 32;
    if (t < 32) sidx[t] = g_idx[(b << 10) + hw0 + t];
    __syncthreads();
#pragma unroll
    for (int r = 0; r < 4; r++) {
        const int nl = r * 8 + wid;
        const float* cbr = cb + (size_t)sidx[nl] * NC;
#pragma unroll
        for (int j = 0; j < 8; j++) {
            const int c = lane + 32 * j;
            S[c][nl] = cbr[c];
        }
    }
    __syncthreads();
    float* ob = out + ((size_t)b << 18);
#pragma unroll
    for (int i = 0; i < 32; i++) {
        const int c = i * 8 + wid;
        ob[(c << 10) + hw0 + lane] = S[c][lane];
    }
}

__global__ void vq_idx_out(float* __restrict__ out) {
    int n = blockIdx.x * blockDim.x + threadIdx.x;
    out[ZQ_ELEMS + n] = (float)g_idx[n];
}

extern "C" void kernel_launch(void* const* d_in, const int* in_sizes, int n_in,
                              void* d_out, int out_size) {
    const float* z  = (const float*)d_in[0];
    const float* cb = (const float*)d_in[1];
    if (n_in >= 2 && in_sizes[0] == NK * NC && in_sizes[1] == NPTS * NC) {
        const float* tmp = z; z = cb; cb = tmp;
    }
    float* out = (float*)d_out;

    cudaFuncSetAttribute(vq_gemm, cudaFuncAttributeMaxDynamicSharedMemorySize, SMEM_SZ);

    prep_cb<<<NK / 8, 256>>>(cb);
    prep_z<<<dim3(32, 16), 256>>>(z);
    vq_gemm<<<dim3(NK / TN, NPTS / TM), 128, SMEM_SZ>>>();
    vq_select<<<NPTS / 8, 256>>>(cb);
    vq_gather<<<dim3(32, 16), 256>>>(cb, out);
    if (out_size >= ZQ_ELEMS + NPTS)
        vq_idx_out<<<NPTS / 256, 256>>>(out);
}

// round 15
// speedup vs baseline: 1.7138x; 1.7138x over previous
#include <cuda_runtime.h>
#include <cuda_bf16.h>
#include <float.h>
#include <stdint.h>

// VectorQuantize: z[16,256,32,32] f32, codebook[8192,256] f32
// bf16 mma.sync GEMM (64x64 warp tile, 4 warps) -> per-(row,tile) min + mask
// -> warp/row select + exact fp32 refine -> transposed gather (+idx tail).
// R15 = R12 champion + idx tail folded into vq_gather.

#define NPTS 16384
#define NC   256
#define NK   8192
#define ZQ_ELEMS 4194304
#define TM 128
#define TN 128
#define NTILE (NK / TN)      // 64
#define MARGIN 8e-3f

// ---------------- scratch ----------------
__device__ unsigned short g_ah[NPTS * NC];    // bf16(z)
__device__ unsigned short g_bh[NK * NC];      // bf16(-2cb)
__device__ float g_zf[NPTS * NC];             // fp32 z rows (refine)
__device__ float g_zn[NPTS];
__device__ float g_cn[NK];                    // |cb|^2
__device__ float g_tmin[(size_t)NPTS * NTILE];
__device__ unsigned g_tmask[(size_t)NPTS * NTILE * 4];
__device__ int g_idx[NPTS];

// smem layout for vq_gemm
#define SROWMIN 65536   // 128 x u32
#define SMASK   66048   // 128 x 4 x u32
#define SMEM_SZ 68608

// ---------------- PTX helpers ----------------
__device__ __forceinline__ uint32_t smem_u32(const void* p) {
    uint32_t a;
    asm("{ .reg .u64 t; cvta.to.shared.u64 t, %1; cvt.u32.u64 %0, t; }" : "=r"(a) : "l"(p));
    return a;
}
#define CP_ASYNC16(sm, gp) \
    asm volatile("cp.async.cg.shared.global [%0], [%1], 16;" :: "r"(sm), "l"(gp) : "memory")
#define CP_COMMIT() asm volatile("cp.async.commit_group;" ::: "memory")
#define CP_WAIT(n)  asm volatile("cp.async.wait_group %0;" :: "n"(n) : "memory")
#define LDSM_X4(r0, r1, r2, r3, ad) \
    asm volatile("ldmatrix.sync.aligned.m8n8.x4.shared.b16 {%0,%1,%2,%3}, [%4];" \
                 : "=r"(r0), "=r"(r1), "=r"(r2), "=r"(r3) : "r"(ad))
#define MMA16816(d, a0, a1, a2, a3, b0, b1) \
    asm volatile("mma.sync.aligned.m16n8k16.row.col.f32.bf16.bf16.f32 " \
                 "{%0,%1,%2,%3}, {%4,%5,%6,%7}, {%8,%9}, {%0,%1,%2,%3};" \
                 : "+f"((d)[0]), "+f"((d)[1]), "+f"((d)[2]), "+f"((d)[3]) \
                 : "r"(a0), "r"(a1), "r"(a2), "r"(a3), "r"(b0), "r"(b1))

__device__ __forceinline__ uint32_t fenc(float f) {
    uint32_t b = __float_as_uint(f);
    return (b & 0x80000000u) ? ~b : (b | 0x80000000u);
}
__device__ __forceinline__ float fdec(uint32_t u) {
    uint32_t b = (u & 0x80000000u) ? (u & 0x7FFFFFFFu) : ~u;
    return __uint_as_float(b);
}

// ---------------- prep_cb: warp per row, vectorized ----------------
__global__ void __launch_bounds__(256) prep_cb(const float* __restrict__ cb) {
    const int lane = threadIdx.x & 31, wid = threadIdx.x >> 5;
    const int k = blockIdx.x * 8 + wid;
    const float4* row = (const float4*)(cb + (size_t)k * NC);
    float4 v0 = row[lane * 2], v1 = row[lane * 2 + 1];
    float s = v0.x * v0.x + v0.y * v0.y + v0.z * v0.z + v0.w * v0.w
            + v1.x * v1.x + v1.y * v1.y + v1.z * v1.z + v1.w * v1.w;
    uint4 pk;
    {
        uint32_t a, b, c, d;
        asm("cvt.rn.bf16x2.f32 %0, %1, %2;" : "=r"(a) : "f"(-2.0f * v0.y), "f"(-2.0f * v0.x));
        asm("cvt.rn.bf16x2.f32 %0, %1, %2;" : "=r"(b) : "f"(-2.0f * v0.w), "f"(-2.0f * v0.z));
        asm("cvt.rn.bf16x2.f32 %0, %1, %2;" : "=r"(c) : "f"(-2.0f * v1.y), "f"(-2.0f * v1.x));
        asm("cvt.rn.bf16x2.f32 %0, %1, %2;" : "=r"(d) : "f"(-2.0f * v1.w), "f"(-2.0f * v1.z));
        pk.x = a; pk.y = b; pk.z = c; pk.w = d;
    }
    *(uint4*)(g_bh + (size_t)k * NC + lane * 8) = pk;
#pragma unroll
    for (int o = 16; o > 0; o >>= 1) s += __shfl_xor_sync(0xffffffffu, s, o);
    if (lane == 0) g_cn[k] = s;
}

// ---------------- prep_z: transposed, coalesced both sides ----------------
__global__ void __launch_bounds__(256) prep_z(const float* __restrict__ z) {
    __shared__ float S[256][33];
    const int t = threadIdx.x, lane = t & 31, wid = t >> 5;
    const int b = blockIdx.y, hw0 = blockIdx.x * 32;
    const float* zb = z + ((size_t)b << 18);
#pragma unroll
    for (int i = 0; i < 32; i++) {
        const int c = i * 8 + wid;
        S[c][lane] = zb[(c << 10) + hw0 + lane];
    }
    __syncthreads();
#pragma unroll
    for (int r = 0; r < 4; r++) {
        const int nl = r * 8 + wid;
        const int n = (b << 10) + hw0 + nl;
        float sum = 0.f;
#pragma unroll
        for (int j = 0; j < 8; j++) {
            const int c = lane + 32 * j;
            const float v = S[c][nl];
            sum += v * v;
            g_zf[(size_t)n * NC + c] = v;
            __nv_bfloat16 h = __float2bfloat16_rn(v);
            g_ah[(size_t)n * NC + c] = *(unsigned short*)&h;
        }
#pragma unroll
        for (int o = 16; o > 0; o >>= 1) sum += __shfl_xor_sync(0xffffffffu, sum, o);
        if (lane == 0) g_zn[n] = sum;
    }
}

// ---------------- GEMM: 128x128 CTA, 4 warps, 64x64 warp tile (R12) ----------------
__device__ __forceinline__ void issue_loads(uint32_t sb, int buf,
                                            const unsigned short* A, const unsigned short* B,
                                            int kchunk, int t) {
    uint32_t ab = sb + buf * 32768;
    uint32_t bb = ab + 16384;
#pragma unroll
    for (int i = 0; i < 8; i++) {
        int e = i * 128 + t;                 // 0..1023
        int r = e >> 3, ck = e & 7;
        int sw = (ck * 16) ^ ((r & 7) * 16);
        CP_ASYNC16(ab + r * 128 + sw, A + (size_t)r * NC + kchunk * 64 + ck * 8);
        CP_ASYNC16(bb + r * 128 + sw, B + (size_t)r * NC + kchunk * 64 + ck * 8);
    }
}

__global__ void __launch_bounds__(128) vq_gemm() {
    extern __shared__ char smem[];
    const uint32_t sb = smem_u32(smem);
    const int t = threadIdx.x;
    const int lane = t & 31, wid = t >> 5;
    const int warp_m = wid >> 1, warp_n = wid & 1;   // 2x2 warps -> 64x64 per warp
    const int tile = blockIdx.x;
    const int col0 = tile * TN;
    const int row0 = blockIdx.y * TM;
    const unsigned short* A = g_ah + (size_t)row0 * NC;
    const unsigned short* B = g_bh + (size_t)col0 * NC;

    uint32_t* rowmin = (uint32_t*)(smem + SROWMIN);
    uint32_t* maskw  = (uint32_t*)(smem + SMASK);
    rowmin[t] = fenc(FLT_MAX);
#pragma unroll
    for (int i = 0; i < 4; i++) maskw[i * 128 + t] = 0;

    float d[4][8][4];
#pragma unroll
    for (int i = 0; i < 4; i++)
#pragma unroll
        for (int j = 0; j < 8; j++)
#pragma unroll
            for (int q = 0; q < 4; q++) d[i][j][q] = 0.f;

    issue_loads(sb, 0, A, B, 0, t);
    CP_COMMIT();

    for (int kc = 0; kc < 4; kc++) {
        if (kc < 3) {
            issue_loads(sb, (kc + 1) & 1, A, B, kc + 1, t);
            CP_COMMIT();
            CP_WAIT(1);
        } else {
            CP_WAIT(0);
        }
        __syncthreads();

        const uint32_t Ab = sb + (kc & 1) * 32768;
        const uint32_t Bb = Ab + 16384;
#pragma unroll
        for (int ks = 0; ks < 4; ks++) {
            const int c2 = ks * 32 + (lane >> 4) * 16;
            uint32_t a[4][4];
#pragma unroll
            for (int mt = 0; mt < 4; mt++) {
                int row = warp_m * 64 + mt * 16 + (lane & 15);
                uint32_t ad = Ab + row * 128 + (c2 ^ ((row & 7) * 16));
                LDSM_X4(a[mt][0], a[mt][1], a[mt][2], a[mt][3], ad);
            }
            uint32_t bq[4][4];
#pragma unroll
            for (int np = 0; np < 4; np++) {
                int brow = warp_n * 64 + np * 16 + (lane & 15);
                uint32_t bd = Bb + brow * 128 + (c2 ^ ((brow & 7) * 16));
                LDSM_X4(bq[np][0], bq[np][1], bq[np][2], bq[np][3], bd);
            }
#pragma unroll
            for (int mt = 0; mt < 4; mt++)
#pragma unroll
                for (int np = 0; np < 4; np++) {
                    MMA16816(d[mt][np * 2],     a[mt][0], a[mt][1], a[mt][2], a[mt][3],
                             bq[np][0], bq[np][2]);
                    MMA16816(d[mt][np * 2 + 1], a[mt][0], a[mt][1], a[mt][2], a[mt][3],
                             bq[np][1], bq[np][3]);
                }
        }
        __syncthreads();
    }

    // ---- summary epilogue ----
    const int g = lane >> 2, tig = lane & 3;
#pragma unroll
    for (int nt = 0; nt < 8; nt++) {
        const int scol = col0 + warp_n * 64 + nt * 8 + 2 * tig;
        const float cn0 = __ldg(&g_cn[scol]);
        const float cn1 = __ldg(&g_cn[scol + 1]);
#pragma unroll
        for (int mt = 0; mt < 4; mt++) {
            d[mt][nt][0] += cn0; d[mt][nt][1] += cn1;
            d[mt][nt][2] += cn0; d[mt][nt][3] += cn1;
        }
    }
#pragma unroll
    for (int mt = 0; mt < 4; mt++) {
        const int r0 = warp_m * 64 + mt * 16 + g;
        float mn0 = FLT_MAX, mn1 = FLT_MAX;
#pragma unroll
        for (int nt = 0; nt < 8; nt++) {
            mn0 = fminf(mn0, fminf(d[mt][nt][0], d[mt][nt][1]));
            mn1 = fminf(mn1, fminf(d[mt][nt][2], d[mt][nt][3]));
        }
        atomicMin(&rowmin[r0],     fenc(mn0));
        atomicMin(&rowmin[r0 + 8], fenc(mn1));
    }
    __syncthreads();
#pragma unroll
    for (int mt = 0; mt < 4; mt++) {
        const int r0 = warp_m * 64 + mt * 16 + g;
        const float th0 = fdec(rowmin[r0]) + MARGIN;
        const float th1 = fdec(rowmin[r0 + 8]) + MARGIN;
#pragma unroll
        for (int nt = 0; nt < 8; nt++) {
            const int c = warp_n * 64 + nt * 8 + 2 * tig;
            if (d[mt][nt][0] <= th0) atomicOr(&maskw[r0 * 4 + (c >> 5)], 1u << (c & 31));
            if (d[mt][nt][1] <= th0) atomicOr(&maskw[r0 * 4 + ((c + 1) >> 5)], 1u << ((c + 1) & 31));
            if (d[mt][nt][2] <= th1) atomicOr(&maskw[(r0 + 8) * 4 + (c >> 5)], 1u << (c & 31));
            if (d[mt][nt][3] <= th1) atomicOr(&maskw[(r0 + 8) * 4 + ((c + 1) >> 5)], 1u << ((c + 1) & 31));
        }
    }
    __syncthreads();
    g_tmin[(size_t)(row0 + t) * NTILE + tile] = fdec(rowmin[t]);
#pragma unroll
    for (int i = 0; i < 4; i++) {
        int e = i * 128 + t;         // 0..511
        int r = e >> 2, w = e & 3;
        g_tmask[((size_t)(row0 + r) * NTILE + tile) * 4 + w] = maskw[r * 4 + w];
    }
}

// ---------------- select + exact fp32 refine: one warp per row ----------------
__global__ void __launch_bounds__(256) vq_select(const float* __restrict__ cb) {
    const int lane = threadIdx.x & 31;
    const int row = blockIdx.x * 8 + (threadIdx.x >> 5);

    const float* tm = g_tmin + (size_t)row * NTILE;
    const float v0 = tm[lane], v1 = tm[lane + 32];
    float m = fminf(v0, v1);
#pragma unroll
    for (int o = 16; o > 0; o >>= 1) m = fminf(m, __shfl_xor_sync(0xffffffffu, m, o));
    const float thr = m + MARGIN;

    float z8[8];
#pragma unroll
    for (int i = 0; i < 8; i++) z8[i] = g_zf[(size_t)row * NC + lane * 8 + i];
    const float zn = g_zn[row];

    float bv = FLT_MAX;
    int bi = 0x7fffffff;

    unsigned bal[2];
    bal[0] = __ballot_sync(0xffffffffu, v0 <= thr);
    bal[1] = __ballot_sync(0xffffffffu, v1 <= thr);
#pragma unroll
    for (int p = 0; p < 2; p++) {
        unsigned bits = bal[p];
        while (bits) {
            const int tile = p * 32 + (__ffs(bits) - 1);
            bits &= bits - 1;
            const uint4 mk = *(const uint4*)(g_tmask + ((size_t)row * NTILE + tile) * 4);
            unsigned w[4] = { mk.x, mk.y, mk.z, mk.w };
#pragma unroll
            for (int wi = 0; wi < 4; wi++) {
                unsigned ww = w[wi];
                while (ww) {
                    const int b = __ffs(ww) - 1;
                    ww &= ww - 1;
                    const int k = tile * TN + wi * 32 + b;
                    const float* cbr = cb + (size_t)k * NC + lane * 8;
                    float s = 0.f;
#pragma unroll
                    for (int i = 0; i < 8; i++) s = fmaf(z8[i], -2.0f * cbr[i], s);
#pragma unroll
                    for (int o = 16; o > 0; o >>= 1) s += __shfl_xor_sync(0xffffffffu, s, o);
                    const float dd = (s + zn) + g_cn[k];
                    if (dd < bv || (dd == bv && k < bi)) { bv = dd; bi = k; }
                }
            }
        }
    }
    if (lane == 0) g_idx[row] = bi;
}

// ---------------- transposed gather (+ idx tail) ----------------
__global__ void __launch_bounds__(256) vq_gather(const float* __restrict__ cb,
                                                 float* __restrict__ out, int emit_idx) {
    __shared__ float S[256][33];
    __shared__ int sidx[32];
    const int t = threadIdx.x, lane = t & 31, wid = t >> 5;
    const int b = blockIdx.y, hw0 = blockIdx.x * 32;
    if (t < 32) sidx[t] = g_idx[(b << 10) + hw0 + t];
    __syncthreads();
#pragma unroll
    for (int r = 0; r < 4; r++) {
        const int nl = r * 8 + wid;
        const float* cbr = cb + (size_t)sidx[nl] * NC;
#pragma unroll
        for (int j = 0; j < 8; j++) {
            const int c = lane + 32 * j;
            S[c][nl] = cbr[c];
        }
    }
    __syncthreads();
    float* ob = out + ((size_t)b << 18);
#pragma unroll
    for (int i = 0; i < 32; i++) {
        const int c = i * 8 + wid;
        ob[(c << 10) + hw0 + lane] = S[c][lane];
    }
    if (emit_idx && t < 32)
        out[ZQ_ELEMS + (b << 10) + hw0 + t] = (float)sidx[t];
}

extern "C" void kernel_launch(void* const* d_in, const int* in_sizes, int n_in,
                              void* d_out, int out_size) {
    const float* z  = (const float*)d_in[0];
    const float* cb = (const float*)d_in[1];
    if (n_in >= 2 && in_sizes[0] == NK * NC && in_sizes[1] == NPTS * NC) {
        const float* tmp = z; z = cb; cb = tmp;
    }
    float* out = (float*)d_out;

    cudaFuncSetAttribute(vq_gemm, cudaFuncAttributeMaxDynamicSharedMemorySize, SMEM_SZ);

    prep_cb<<<NK / 8, 256>>>(cb);
    prep_z<<<dim3(32, 16), 256>>>(z);
    vq_gemm<<<dim3(NK / TN, NPTS / TM), 128, SMEM_SZ>>>();
    vq_select<<<NPTS / 8, 256>>>(cb);
    vq_gather<<<dim3(32, 16), 256>>>(cb, out, out_size >= ZQ_ELEMS + NPTS);
}

// round 16
// speedup vs baseline: 1.7338x; 1.0117x over previous
#include <cuda_runtime.h>
#include <cuda_bf16.h>
#include <float.h>
#include <stdint.h>

// VectorQuantize: z[16,256,32,32] f32, codebook[8192,256] f32
// bf16 mma.sync GEMM (64x64 warp tile, 4 warps) -> per-(row,tile) min + mask
// -> warp/row select + exact fp32 refine -> transposed gather (+idx tail).
// R16 = R15 champion + __launch_bounds__(128, 3) on vq_gemm (occupancy experiment).

#define NPTS 16384
#define NC   256
#define NK   8192
#define ZQ_ELEMS 4194304
#define TM 128
#define TN 128
#define NTILE (NK / TN)      // 64
#define MARGIN 8e-3f

// ---------------- scratch ----------------
__device__ unsigned short g_ah[NPTS * NC];    // bf16(z)
__device__ unsigned short g_bh[NK * NC];      // bf16(-2cb)
__device__ float g_zf[NPTS * NC];             // fp32 z rows (refine)
__device__ float g_zn[NPTS];
__device__ float g_cn[NK];                    // |cb|^2
__device__ float g_tmin[(size_t)NPTS * NTILE];
__device__ unsigned g_tmask[(size_t)NPTS * NTILE * 4];
__device__ int g_idx[NPTS];

// smem layout for vq_gemm
#define SROWMIN 65536   // 128 x u32
#define SMASK   66048   // 128 x 4 x u32
#define SMEM_SZ 68608

// ---------------- PTX helpers ----------------
__device__ __forceinline__ uint32_t smem_u32(const void* p) {
    uint32_t a;
    asm("{ .reg .u64 t; cvta.to.shared.u64 t, %1; cvt.u32.u64 %0, t; }" : "=r"(a) : "l"(p));
    return a;
}
#define CP_ASYNC16(sm, gp) \
    asm volatile("cp.async.cg.shared.global [%0], [%1], 16;" :: "r"(sm), "l"(gp) : "memory")
#define CP_COMMIT() asm volatile("cp.async.commit_group;" ::: "memory")
#define CP_WAIT(n)  asm volatile("cp.async.wait_group %0;" :: "n"(n) : "memory")
#define LDSM_X4(r0, r1, r2, r3, ad) \
    asm volatile("ldmatrix.sync.aligned.m8n8.x4.shared.b16 {%0,%1,%2,%3}, [%4];" \
                 : "=r"(r0), "=r"(r1), "=r"(r2), "=r"(r3) : "r"(ad))
#define MMA16816(d, a0, a1, a2, a3, b0, b1) \
    asm volatile("mma.sync.aligned.m16n8k16.row.col.f32.bf16.bf16.f32 " \
                 "{%0,%1,%2,%3}, {%4,%5,%6,%7}, {%8,%9}, {%0,%1,%2,%3};" \
                 : "+f"((d)[0]), "+f"((d)[1]), "+f"((d)[2]), "+f"((d)[3]) \
                 : "r"(a0), "r"(a1), "r"(a2), "r"(a3), "r"(b0), "r"(b1))

__device__ __forceinline__ uint32_t fenc(float f) {
    uint32_t b = __float_as_uint(f);
    return (b & 0x80000000u) ? ~b : (b | 0x80000000u);
}
__device__ __forceinline__ float fdec(uint32_t u) {
    uint32_t b = (u & 0x80000000u) ? (u & 0x7FFFFFFFu) : ~u;
    return __uint_as_float(b);
}

// ---------------- prep_cb: warp per row, vectorized ----------------
__global__ void __launch_bounds__(256) prep_cb(const float* __restrict__ cb) {
    const int lane = threadIdx.x & 31, wid = threadIdx.x >> 5;
    const int k = blockIdx.x * 8 + wid;
    const float4* row = (const float4*)(cb + (size_t)k * NC);
    float4 v0 = row[lane * 2], v1 = row[lane * 2 + 1];
    float s = v0.x * v0.x + v0.y * v0.y + v0.z * v0.z + v0.w * v0.w
            + v1.x * v1.x + v1.y * v1.y + v1.z * v1.z + v1.w * v1.w;
    uint4 pk;
    {
        uint32_t a, b, c, d;
        asm("cvt.rn.bf16x2.f32 %0, %1, %2;" : "=r"(a) : "f"(-2.0f * v0.y), "f"(-2.0f * v0.x));
        asm("cvt.rn.bf16x2.f32 %0, %1, %2;" : "=r"(b) : "f"(-2.0f * v0.w), "f"(-2.0f * v0.z));
        asm("cvt.rn.bf16x2.f32 %0, %1, %2;" : "=r"(c) : "f"(-2.0f * v1.y), "f"(-2.0f * v1.x));
        asm("cvt.rn.bf16x2.f32 %0, %1, %2;" : "=r"(d) : "f"(-2.0f * v1.w), "f"(-2.0f * v1.z));
        pk.x = a; pk.y = b; pk.z = c; pk.w = d;
    }
    *(uint4*)(g_bh + (size_t)k * NC + lane * 8) = pk;
#pragma unroll
    for (int o = 16; o > 0; o >>= 1) s += __shfl_xor_sync(0xffffffffu, s, o);
    if (lane == 0) g_cn[k] = s;
}

// ---------------- prep_z: transposed, coalesced both sides ----------------
__global__ void __launch_bounds__(256) prep_z(const float* __restrict__ z) {
    __shared__ float S[256][33];
    const int t = threadIdx.x, lane = t & 31, wid = t >> 5;
    const int b = blockIdx.y, hw0 = blockIdx.x * 32;
    const float* zb = z + ((size_t)b << 18);
#pragma unroll
    for (int i = 0; i < 32; i++) {
        const int c = i * 8 + wid;
        S[c][lane] = zb[(c << 10) + hw0 + lane];
    }
    __syncthreads();
#pragma unroll
    for (int r = 0; r < 4; r++) {
        const int nl = r * 8 + wid;
        const int n = (b << 10) + hw0 + nl;
        float sum = 0.f;
#pragma unroll
        for (int j = 0; j < 8; j++) {
            const int c = lane + 32 * j;
            const float v = S[c][nl];
            sum += v * v;
            g_zf[(size_t)n * NC + c] = v;
            __nv_bfloat16 h = __float2bfloat16_rn(v);
            g_ah[(size_t)n * NC + c] = *(unsigned short*)&h;
        }
#pragma unroll
        for (int o = 16; o > 0; o >>= 1) sum += __shfl_xor_sync(0xffffffffu, sum, o);
        if (lane == 0) g_zn[n] = sum;
    }
}

// ---------------- GEMM: 128x128 CTA, 4 warps, 64x64 warp tile ----------------
__device__ __forceinline__ void issue_loads(uint32_t sb, int buf,
                                            const unsigned short* A, const unsigned short* B,
                                            int kchunk, int t) {
    uint32_t ab = sb + buf * 32768;
    uint32_t bb = ab + 16384;
#pragma unroll
    for (int i = 0; i < 8; i++) {
        int e = i * 128 + t;                 // 0..1023
        int r = e >> 3, ck = e & 7;
        int sw = (ck * 16) ^ ((r & 7) * 16);
        CP_ASYNC16(ab + r * 128 + sw, A + (size_t)r * NC + kchunk * 64 + ck * 8);
        CP_ASYNC16(bb + r * 128 + sw, B + (size_t)r * NC + kchunk * 64 + ck * 8);
    }
}

__global__ void __launch_bounds__(128, 3) vq_gemm() {
    extern __shared__ char smem[];
    const uint32_t sb = smem_u32(smem);
    const int t = threadIdx.x;
    const int lane = t & 31, wid = t >> 5;
    const int warp_m = wid >> 1, warp_n = wid & 1;   // 2x2 warps -> 64x64 per warp
    const int tile = blockIdx.x;
    const int col0 = tile * TN;
    const int row0 = blockIdx.y * TM;
    const unsigned short* A = g_ah + (size_t)row0 * NC;
    const unsigned short* B = g_bh + (size_t)col0 * NC;

    uint32_t* rowmin = (uint32_t*)(smem + SROWMIN);
    uint32_t* maskw  = (uint32_t*)(smem + SMASK);
    rowmin[t] = fenc(FLT_MAX);
#pragma unroll
    for (int i = 0; i < 4; i++) maskw[i * 128 + t] = 0;

    float d[4][8][4];
#pragma unroll
    for (int i = 0; i < 4; i++)
#pragma unroll
        for (int j = 0; j < 8; j++)
#pragma unroll
            for (int q = 0; q < 4; q++) d[i][j][q] = 0.f;

    issue_loads(sb, 0, A, B, 0, t);
    CP_COMMIT();

    for (int kc = 0; kc < 4; kc++) {
        if (kc < 3) {
            issue_loads(sb, (kc + 1) & 1, A, B, kc + 1, t);
            CP_COMMIT();
            CP_WAIT(1);
        } else {
            CP_WAIT(0);
        }
        __syncthreads();

        const uint32_t Ab = sb + (kc & 1) * 32768;
        const uint32_t Bb = Ab + 16384;
#pragma unroll
        for (int ks = 0; ks < 4; ks++) {
            const int c2 = ks * 32 + (lane >> 4) * 16;
            uint32_t a[4][4];
#pragma unroll
            for (int mt = 0; mt < 4; mt++) {
                int row = warp_m * 64 + mt * 16 + (lane & 15);
                uint32_t ad = Ab + row * 128 + (c2 ^ ((row & 7) * 16));
                LDSM_X4(a[mt][0], a[mt][1], a[mt][2], a[mt][3], ad);
            }
            uint32_t bq[4][4];
#pragma unroll
            for (int np = 0; np < 4; np++) {
                int brow = warp_n * 64 + np * 16 + (lane & 15);
                uint32_t bd = Bb + brow * 128 + (c2 ^ ((brow & 7) * 16));
                LDSM_X4(bq[np][0], bq[np][1], bq[np][2], bq[np][3], bd);
            }
#pragma unroll
            for (int mt = 0; mt < 4; mt++)
#pragma unroll
                for (int np = 0; np < 4; np++) {
                    MMA16816(d[mt][np * 2],     a[mt][0], a[mt][1], a[mt][2], a[mt][3],
                             bq[np][0], bq[np][2]);
                    MMA16816(d[mt][np * 2 + 1], a[mt][0], a[mt][1], a[mt][2], a[mt][3],
                             bq[np][1], bq[np][3]);
                }
        }
        __syncthreads();
    }

    // ---- summary epilogue ----
    const int g = lane >> 2, tig = lane & 3;
#pragma unroll
    for (int nt = 0; nt < 8; nt++) {
        const int scol = col0 + warp_n * 64 + nt * 8 + 2 * tig;
        const float cn0 = __ldg(&g_cn[scol]);
        const float cn1 = __ldg(&g_cn[scol + 1]);
#pragma unroll
        for (int mt = 0; mt < 4; mt++) {
            d[mt][nt][0] += cn0; d[mt][nt][1] += cn1;
            d[mt][nt][2] += cn0; d[mt][nt][3] += cn1;
        }
    }
#pragma unroll
    for (int mt = 0; mt < 4; mt++) {
        const int r0 = warp_m * 64 + mt * 16 + g;
        float mn0 = FLT_MAX, mn1 = FLT_MAX;
#pragma unroll
        for (int nt = 0; nt < 8; nt++) {
            mn0 = fminf(mn0, fminf(d[mt][nt][0], d[mt][nt][1]));
            mn1 = fminf(mn1, fminf(d[mt][nt][2], d[mt][nt][3]));
        }
        atomicMin(&rowmin[r0],     fenc(mn0));
        atomicMin(&rowmin[r0 + 8], fenc(mn1));
    }
    __syncthreads();
#pragma unroll
    for (int mt = 0; mt < 4; mt++) {
        const int r0 = warp_m * 64 + mt * 16 + g;
        const float th0 = fdec(rowmin[r0]) + MARGIN;
        const float th1 = fdec(rowmin[r0 + 8]) + MARGIN;
#pragma unroll
        for (int nt = 0; nt < 8; nt++) {
            const int c = warp_n * 64 + nt * 8 + 2 * tig;
            if (d[mt][nt][0] <= th0) atomicOr(&maskw[r0 * 4 + (c >> 5)], 1u << (c & 31));
            if (d[mt][nt][1] <= th0) atomicOr(&maskw[r0 * 4 + ((c + 1) >> 5)], 1u << ((c + 1) & 31));
            if (d[mt][nt][2] <= th1) atomicOr(&maskw[(r0 + 8) * 4 + (c >> 5)], 1u << (c & 31));
            if (d[mt][nt][3] <= th1) atomicOr(&maskw[(r0 + 8) * 4 + ((c + 1) >> 5)], 1u << ((c + 1) & 31));
        }
    }
    __syncthreads();
    g_tmin[(size_t)(row0 + t) * NTILE + tile] = fdec(rowmin[t]);
#pragma unroll
    for (int i = 0; i < 4; i++) {
        int e = i * 128 + t;         // 0..511
        int r = e >> 2, w = e & 3;
        g_tmask[((size_t)(row0 + r) * NTILE + tile) * 4 + w] = maskw[r * 4 + w];
    }
}

// ---------------- select + exact fp32 refine: one warp per row ----------------
__global__ void __launch_bounds__(256) vq_select(const float* __restrict__ cb) {
    const int lane = threadIdx.x & 31;
    const int row = blockIdx.x * 8 + (threadIdx.x >> 5);

    const float* tm = g_tmin + (size_t)row * NTILE;
    const float v0 = tm[lane], v1 = tm[lane + 32];
    float m = fminf(v0, v1);
#pragma unroll
    for (int o = 16; o > 0; o >>= 1) m = fminf(m, __shfl_xor_sync(0xffffffffu, m, o));
    const float thr = m + MARGIN;

    float z8[8];
#pragma unroll
    for (int i = 0; i < 8; i++) z8[i] = g_zf[(size_t)row * NC + lane * 8 + i];
    const float zn = g_zn[row];

    float bv = FLT_MAX;
    int bi = 0x7fffffff;

    unsigned bal[2];
    bal[0] = __ballot_sync(0xffffffffu, v0 <= thr);
    bal[1] = __ballot_sync(0xffffffffu, v1 <= thr);
#pragma unroll
    for (int p = 0; p < 2; p++) {
        unsigned bits = bal[p];
        while (bits) {
            const int tile = p * 32 + (__ffs(bits) - 1);
            bits &= bits - 1;
            const uint4 mk = *(const uint4*)(g_tmask + ((size_t)row * NTILE + tile) * 4);
            unsigned w[4] = { mk.x, mk.y, mk.z, mk.w };
#pragma unroll
            for (int wi = 0; wi < 4; wi++) {
                unsigned ww = w[wi];
                while (ww) {
                    const int b = __ffs(ww) - 1;
                    ww &= ww - 1;
                    const int k = tile * TN + wi * 32 + b;
                    const float* cbr = cb + (size_t)k * NC + lane * 8;
                    float s = 0.f;
#pragma unroll
                    for (int i = 0; i < 8; i++) s = fmaf(z8[i], -2.0f * cbr[i], s);
#pragma unroll
                    for (int o = 16; o > 0; o >>= 1) s += __shfl_xor_sync(0xffffffffu, s, o);
                    const float dd = (s + zn) + g_cn[k];
                    if (dd < bv || (dd == bv && k < bi)) { bv = dd; bi = k; }
                }
            }
        }
    }
    if (lane == 0) g_idx[row] = bi;
}

// ---------------- transposed gather (+ idx tail) ----------------
__global__ void __launch_bounds__(256) vq_gather(const float* __restrict__ cb,
                                                 float* __restrict__ out, int emit_idx) {
    __shared__ float S[256][33];
    __shared__ int sidx[32];
    const int t = threadIdx.x, lane = t & 31, wid = t >> 5;
    const int b = blockIdx.y, hw0 = blockIdx.x * 32;
    if (t < 32) sidx[t] = g_idx[(b << 10) + hw0 + t];
    __syncthreads();
#pragma unroll
    for (int r = 0; r < 4; r++) {
        const int nl = r * 8 + wid;
        const float* cbr = cb + (size_t)sidx[nl] * NC;
#pragma unroll
        for (int j = 0; j < 8; j++) {
            const int c = lane + 32 * j;
            S[c][nl] = cbr[c];
        }
    }
    __syncthreads();
    float* ob = out + ((size_t)b << 18);
#pragma unroll
    for (int i = 0; i < 32; i++) {
        const int c = i * 8 + wid;
        ob[(c << 10) + hw0 + lane] = S[c][lane];
    }
    if (emit_idx && t < 32)
        out[ZQ_ELEMS + (b << 10) + hw0 + t] = (float)sidx[t];
}

extern "C" void kernel_launch(void* const* d_in, const int* in_sizes, int n_in,
                              void* d_out, int out_size) {
    const float* z  = (const float*)d_in[0];
    const float* cb = (const float*)d_in[1];
    if (n_in >= 2 && in_sizes[0] == NK * NC && in_sizes[1] == NPTS * NC) {
        const float* tmp = z; z = cb; cb = tmp;
    }
    float* out = (float*)d_out;

    cudaFuncSetAttribute(vq_gemm, cudaFuncAttributeMaxDynamicSharedMemorySize, SMEM_SZ);

    prep_cb<<<NK / 8, 256>>>(cb);
    prep_z<<<dim3(32, 16), 256>>>(z);
    vq_gemm<<<dim3(NK / TN, NPTS / TM), 128, SMEM_SZ>>>();
    vq_select<<<NPTS / 8, 256>>>(cb);
    vq_gather<<<dim3(32, 16), 256>>>(cb, out, out_size >= ZQ_ELEMS + NPTS);
}

// round 17
// speedup vs baseline: 1.7394x; 1.0032x over previous
#include <cuda_runtime.h>
#include <cuda_bf16.h>
#include <float.h>
#include <stdint.h>

// VectorQuantize: z[16,256,32,32] f32, codebook[8192,256] f32
// bf16 mma.sync GEMM (64x64 warp tile) -> per-(row,tile) min + 128-bit mask
// -> fused select(exact fp32 refine)+gather+idx kernel.
// R17 = R16 champion + vq_select/vq_gather fusion.

#define NPTS 16384
#define NC   256
#define NK   8192
#define ZQ_ELEMS 4194304
#define TM 128
#define TN 128
#define NTILE (NK / TN)      // 64
#define MARGIN 8e-3f

// ---------------- scratch ----------------
__device__ unsigned short g_ah[NPTS * NC];    // bf16(z)
__device__ unsigned short g_bh[NK * NC];      // bf16(-2cb)
__device__ float g_zf[NPTS * NC];             // fp32 z rows (refine)
__device__ float g_zn[NPTS];
__device__ float g_cn[NK];                    // |cb|^2
__device__ float g_tmin[(size_t)NPTS * NTILE];
__device__ unsigned g_tmask[(size_t)NPTS * NTILE * 4];

// smem layout for vq_gemm
#define SROWMIN 65536   // 128 x u32
#define SMASK   66048   // 128 x 4 x u32
#define SMEM_SZ 68608

// ---------------- PTX helpers ----------------
__device__ __forceinline__ uint32_t smem_u32(const void* p) {
    uint32_t a;
    asm("{ .reg .u64 t; cvta.to.shared.u64 t, %1; cvt.u32.u64 %0, t; }" : "=r"(a) : "l"(p));
    return a;
}
#define CP_ASYNC16(sm, gp) \
    asm volatile("cp.async.cg.shared.global [%0], [%1], 16;" :: "r"(sm), "l"(gp) : "memory")
#define CP_COMMIT() asm volatile("cp.async.commit_group;" ::: "memory")
#define CP_WAIT(n)  asm volatile("cp.async.wait_group %0;" :: "n"(n) : "memory")
#define LDSM_X4(r0, r1, r2, r3, ad) \
    asm volatile("ldmatrix.sync.aligned.m8n8.x4.shared.b16 {%0,%1,%2,%3}, [%4];" \
                 : "=r"(r0), "=r"(r1), "=r"(r2), "=r"(r3) : "r"(ad))
#define MMA16816(d, a0, a1, a2, a3, b0, b1) \
    asm volatile("mma.sync.aligned.m16n8k16.row.col.f32.bf16.bf16.f32 " \
                 "{%0,%1,%2,%3}, {%4,%5,%6,%7}, {%8,%9}, {%0,%1,%2,%3};" \
                 : "+f"((d)[0]), "+f"((d)[1]), "+f"((d)[2]), "+f"((d)[3]) \
                 : "r"(a0), "r"(a1), "r"(a2), "r"(a3), "r"(b0), "r"(b1))

__device__ __forceinline__ uint32_t fenc(float f) {
    uint32_t b = __float_as_uint(f);
    return (b & 0x80000000u) ? ~b : (b | 0x80000000u);
}
__device__ __forceinline__ float fdec(uint32_t u) {
    uint32_t b = (u & 0x80000000u) ? (u & 0x7FFFFFFFu) : ~u;
    return __uint_as_float(b);
}

// ---------------- prep_cb: warp per row, vectorized ----------------
__global__ void __launch_bounds__(256) prep_cb(const float* __restrict__ cb) {
    const int lane = threadIdx.x & 31, wid = threadIdx.x >> 5;
    const int k = blockIdx.x * 8 + wid;
    const float4* row = (const float4*)(cb + (size_t)k * NC);
    float4 v0 = row[lane * 2], v1 = row[lane * 2 + 1];
    float s = v0.x * v0.x + v0.y * v0.y + v0.z * v0.z + v0.w * v0.w
            + v1.x * v1.x + v1.y * v1.y + v1.z * v1.z + v1.w * v1.w;
    uint4 pk;
    {
        uint32_t a, b, c, d;
        asm("cvt.rn.bf16x2.f32 %0, %1, %2;" : "=r"(a) : "f"(-2.0f * v0.y), "f"(-2.0f * v0.x));
        asm("cvt.rn.bf16x2.f32 %0, %1, %2;" : "=r"(b) : "f"(-2.0f * v0.w), "f"(-2.0f * v0.z));
        asm("cvt.rn.bf16x2.f32 %0, %1, %2;" : "=r"(c) : "f"(-2.0f * v1.y), "f"(-2.0f * v1.x));
        asm("cvt.rn.bf16x2.f32 %0, %1, %2;" : "=r"(d) : "f"(-2.0f * v1.w), "f"(-2.0f * v1.z));
        pk.x = a; pk.y = b; pk.z = c; pk.w = d;
    }
    *(uint4*)(g_bh + (size_t)k * NC + lane * 8) = pk;
#pragma unroll
    for (int o = 16; o > 0; o >>= 1) s += __shfl_xor_sync(0xffffffffu, s, o);
    if (lane == 0) g_cn[k] = s;
}

// ---------------- prep_z: transposed, coalesced both sides ----------------
__global__ void __launch_bounds__(256) prep_z(const float* __restrict__ z) {
    __shared__ float S[256][33];
    const int t = threadIdx.x, lane = t & 31, wid = t >> 5;
    const int b = blockIdx.y, hw0 = blockIdx.x * 32;
    const float* zb = z + ((size_t)b << 18);
#pragma unroll
    for (int i = 0; i < 32; i++) {
        const int c = i * 8 + wid;
        S[c][lane] = zb[(c << 10) + hw0 + lane];
    }
    __syncthreads();
#pragma unroll
    for (int r = 0; r < 4; r++) {
        const int nl = r * 8 + wid;
        const int n = (b << 10) + hw0 + nl;
        float sum = 0.f;
#pragma unroll
        for (int j = 0; j < 8; j++) {
            const int c = lane + 32 * j;
            const float v = S[c][nl];
            sum += v * v;
            g_zf[(size_t)n * NC + c] = v;
            __nv_bfloat16 h = __float2bfloat16_rn(v);
            g_ah[(size_t)n * NC + c] = *(unsigned short*)&h;
        }
#pragma unroll
        for (int o = 16; o > 0; o >>= 1) sum += __shfl_xor_sync(0xffffffffu, sum, o);
        if (lane == 0) g_zn[n] = sum;
    }
}

// ---------------- GEMM: 128x128 CTA, 4 warps, 64x64 warp tile ----------------
__device__ __forceinline__ void issue_loads(uint32_t sb, int buf,
                                            const unsigned short* A, const unsigned short* B,
                                            int kchunk, int t) {
    uint32_t ab = sb + buf * 32768;
    uint32_t bb = ab + 16384;
#pragma unroll
    for (int i = 0; i < 8; i++) {
        int e = i * 128 + t;                 // 0..1023
        int r = e >> 3, ck = e & 7;
        int sw = (ck * 16) ^ ((r & 7) * 16);
        CP_ASYNC16(ab + r * 128 + sw, A + (size_t)r * NC + kchunk * 64 + ck * 8);
        CP_ASYNC16(bb + r * 128 + sw, B + (size_t)r * NC + kchunk * 64 + ck * 8);
    }
}

__global__ void __launch_bounds__(128, 3) vq_gemm() {
    extern __shared__ char smem[];
    const uint32_t sb = smem_u32(smem);
    const int t = threadIdx.x;
    const int lane = t & 31, wid = t >> 5;
    const int warp_m = wid >> 1, warp_n = wid & 1;   // 2x2 warps -> 64x64 per warp
    const int tile = blockIdx.x;
    const int col0 = tile * TN;
    const int row0 = blockIdx.y * TM;
    const unsigned short* A = g_ah + (size_t)row0 * NC;
    const unsigned short* B = g_bh + (size_t)col0 * NC;

    uint32_t* rowmin = (uint32_t*)(smem + SROWMIN);
    uint32_t* maskw  = (uint32_t*)(smem + SMASK);
    rowmin[t] = fenc(FLT_MAX);
#pragma unroll
    for (int i = 0; i < 4; i++) maskw[i * 128 + t] = 0;

    float d[4][8][4];
#pragma unroll
    for (int i = 0; i < 4; i++)
#pragma unroll
        for (int j = 0; j < 8; j++)
#pragma unroll
            for (int q = 0; q < 4; q++) d[i][j][q] = 0.f;

    issue_loads(sb, 0, A, B, 0, t);
    CP_COMMIT();

    for (int kc = 0; kc < 4; kc++) {
        if (kc < 3) {
            issue_loads(sb, (kc + 1) & 1, A, B, kc + 1, t);
            CP_COMMIT();
            CP_WAIT(1);
        } else {
            CP_WAIT(0);
        }
        __syncthreads();

        const uint32_t Ab = sb + (kc & 1) * 32768;
        const uint32_t Bb = Ab + 16384;
#pragma unroll
        for (int ks = 0; ks < 4; ks++) {
            const int c2 = ks * 32 + (lane >> 4) * 16;
            uint32_t a[4][4];
#pragma unroll
            for (int mt = 0; mt < 4; mt++) {
                int row = warp_m * 64 + mt * 16 + (lane & 15);
                uint32_t ad = Ab + row * 128 + (c2 ^ ((row & 7) * 16));
                LDSM_X4(a[mt][0], a[mt][1], a[mt][2], a[mt][3], ad);
            }
            uint32_t bq[4][4];
#pragma unroll
            for (int np = 0; np < 4; np++) {
                int brow = warp_n * 64 + np * 16 + (lane & 15);
                uint32_t bd = Bb + brow * 128 + (c2 ^ ((brow & 7) * 16));
                LDSM_X4(bq[np][0], bq[np][1], bq[np][2], bq[np][3], bd);
            }
#pragma unroll
            for (int mt = 0; mt < 4; mt++)
#pragma unroll
                for (int np = 0; np < 4; np++) {
                    MMA16816(d[mt][np * 2],     a[mt][0], a[mt][1], a[mt][2], a[mt][3],
                             bq[np][0], bq[np][2]);
                    MMA16816(d[mt][np * 2 + 1], a[mt][0], a[mt][1], a[mt][2], a[mt][3],
                             bq[np][1], bq[np][3]);
                }
        }
        __syncthreads();
    }

    // ---- summary epilogue ----
    const int g = lane >> 2, tig = lane & 3;
#pragma unroll
    for (int nt = 0; nt < 8; nt++) {
        const int scol = col0 + warp_n * 64 + nt * 8 + 2 * tig;
        const float cn0 = __ldg(&g_cn[scol]);
        const float cn1 = __ldg(&g_cn[scol + 1]);
#pragma unroll
        for (int mt = 0; mt < 4; mt++) {
            d[mt][nt][0] += cn0; d[mt][nt][1] += cn1;
            d[mt][nt][2] += cn0; d[mt][nt][3] += cn1;
        }
    }
#pragma unroll
    for (int mt = 0; mt < 4; mt++) {
        const int r0 = warp_m * 64 + mt * 16 + g;
        float mn0 = FLT_MAX, mn1 = FLT_MAX;
#pragma unroll
        for (int nt = 0; nt < 8; nt++) {
            mn0 = fminf(mn0, fminf(d[mt][nt][0], d[mt][nt][1]));
            mn1 = fminf(mn1, fminf(d[mt][nt][2], d[mt][nt][3]));
        }
        atomicMin(&rowmin[r0],     fenc(mn0));
        atomicMin(&rowmin[r0 + 8], fenc(mn1));
    }
    __syncthreads();
#pragma unroll
    for (int mt = 0; mt < 4; mt++) {
        const int r0 = warp_m * 64 + mt * 16 + g;
        const float th0 = fdec(rowmin[r0]) + MARGIN;
        const float th1 = fdec(rowmin[r0 + 8]) + MARGIN;
#pragma unroll
        for (int nt = 0; nt < 8; nt++) {
            const int c = warp_n * 64 + nt * 8 + 2 * tig;
            if (d[mt][nt][0] <= th0) atomicOr(&maskw[r0 * 4 + (c >> 5)], 1u << (c & 31));
            if (d[mt][nt][1] <= th0) atomicOr(&maskw[r0 * 4 + ((c + 1) >> 5)], 1u << ((c + 1) & 31));
            if (d[mt][nt][2] <= th1) atomicOr(&maskw[(r0 + 8) * 4 + (c >> 5)], 1u << (c & 31));
            if (d[mt][nt][3] <= th1) atomicOr(&maskw[(r0 + 8) * 4 + ((c + 1) >> 5)], 1u << ((c + 1) & 31));
        }
    }
    __syncthreads();
    g_tmin[(size_t)(row0 + t) * NTILE + tile] = fdec(rowmin[t]);
#pragma unroll
    for (int i = 0; i < 4; i++) {
        int e = i * 128 + t;         // 0..511
        int r = e >> 2, w = e & 3;
        g_tmask[((size_t)(row0 + r) * NTILE + tile) * 4 + w] = maskw[r * 4 + w];
    }
}

// ---------------- fused finish: select (exact fp32 refine) + gather + idx ----------------
__global__ void __launch_bounds__(256) vq_finish(const float* __restrict__ cb,
                                                 float* __restrict__ out, int emit_idx) {
    __shared__ float S[256][33];
    __shared__ int sidx[32];
    const int t = threadIdx.x, lane = t & 31, wid = t >> 5;
    const int b = blockIdx.y, hw0 = blockIdx.x * 32;

    // ---- phase 1: select — each warp resolves 4 rows (wid, wid+8, wid+16, wid+24) ----
#pragma unroll
    for (int r = 0; r < 4; r++) {
        const int nl = r * 8 + wid;
        const int row = (b << 10) + hw0 + nl;

        const float* tm = g_tmin + (size_t)row * NTILE;
        const float v0 = tm[lane], v1 = tm[lane + 32];
        float m = fminf(v0, v1);
#pragma unroll
        for (int o = 16; o > 0; o >>= 1) m = fminf(m, __shfl_xor_sync(0xffffffffu, m, o));
        const float thr = m + MARGIN;

        float z8[8];
#pragma unroll
        for (int i = 0; i < 8; i++) z8[i] = g_zf[(size_t)row * NC + lane * 8 + i];
        const float zn = g_zn[row];

        float bv = FLT_MAX;
        int bi = 0x7fffffff;

        unsigned bal[2];
        bal[0] = __ballot_sync(0xffffffffu, v0 <= thr);
        bal[1] = __ballot_sync(0xffffffffu, v1 <= thr);
#pragma unroll
        for (int p = 0; p < 2; p++) {
            unsigned bits = bal[p];
            while (bits) {
                const int tile = p * 32 + (__ffs(bits) - 1);
                bits &= bits - 1;
                const uint4 mk = *(const uint4*)(g_tmask + ((size_t)row * NTILE + tile) * 4);
                unsigned w[4] = { mk.x, mk.y, mk.z, mk.w };
#pragma unroll
                for (int wi = 0; wi < 4; wi++) {
                    unsigned ww = w[wi];
                    while (ww) {
                        const int bb_ = __ffs(ww) - 1;
                        ww &= ww - 1;
                        const int k = tile * TN + wi * 32 + bb_;
                        const float* cbr = cb + (size_t)k * NC + lane * 8;
                        float s = 0.f;
#pragma unroll
                        for (int i = 0; i < 8; i++) s = fmaf(z8[i], -2.0f * cbr[i], s);
#pragma unroll
                        for (int o = 16; o > 0; o >>= 1) s += __shfl_xor_sync(0xffffffffu, s, o);
                        const float dd = (s + zn) + g_cn[k];
                        if (dd < bv || (dd == bv && k < bi)) { bv = dd; bi = k; }
                    }
                }
            }
        }
        if (lane == 0) sidx[nl] = bi;
    }
    __syncthreads();

    // ---- phase 2: gather (transposed, coalesced) + idx tail ----
#pragma unroll
    for (int r = 0; r < 4; r++) {
        const int nl = r * 8 + wid;
        const float* cbr = cb + (size_t)sidx[nl] * NC;
#pragma unroll
        for (int j = 0; j < 8; j++) {
            const int c = lane + 32 * j;
            S[c][nl] = cbr[c];
        }
    }
    __syncthreads();
    float* ob = out + ((size_t)b << 18);
#pragma unroll
    for (int i = 0; i < 32; i++) {
        const int c = i * 8 + wid;
        ob[(c << 10) + hw0 + lane] = S[c][lane];
    }
    if (emit_idx && t < 32)
        out[ZQ_ELEMS + (b << 10) + hw0 + t] = (float)sidx[t];
}

extern "C" void kernel_launch(void* const* d_in, const int* in_sizes, int n_in,
                              void* d_out, int out_size) {
    const float* z  = (const float*)d_in[0];
    const float* cb = (const float*)d_in[1];
    if (n_in >= 2 && in_sizes[0] == NK * NC && in_sizes[1] == NPTS * NC) {
        const float* tmp = z; z = cb; cb = tmp;
    }
    float* out = (float*)d_out;

    cudaFuncSetAttribute(vq_gemm, cudaFuncAttributeMaxDynamicSharedMemorySize, SMEM_SZ);

    prep_cb<<<NK / 8, 256>>>(cb);
    prep_z<<<dim3(32, 16), 256>>>(z);
    vq_gemm<<<dim3(NK / TN, NPTS / TM), 128, SMEM_SZ>>>();
    vq_finish<<<dim3(32, 16), 256>>>(cb, out, out_size >= ZQ_ELEMS + NPTS);
}